// round 11
// baseline (speedup 1.0000x reference)
#include <cuda_runtime.h>

// out[b,c,h,w] = x[b,c,h,w] * (h%3 != 0) * (w%3 != 0)
//
// Unfold(k=2,stride=3,dil=2,pad=1)+fold(identical geometry) == elementwise 0/1
// coverage mask, separable in h,w. Rows h%3==0 are all-zero in the output.
//
// R11: fold the zero-row stores into the live blocks' load-latency shadow.
// Each live thread: issue 4 unconditional LDG.128 (plane-strided, MLP=4),
// then ONE independent 256-bit zero store (fills the wait), then 4 masked
// STG.128. Zero work = 1,441,792 f8 vs 1,376,256 live threads -> remainder
// 65,536 f8 handled by 256 trailing pure-zero blocks.
//
// Geometry: 32768 planes of 32x32 f32; plane = 256 float4 = 1024 floats;
// row = 8 float4 = 4 float8 = one 128B line.
// Live rows/plane: 21 (h = 3k/2+1). Zero rows/plane: 11 (h = 3k).

static constexpr int THREADS     = 256;
static constexpr int PLANES      = 64 * 512;                    // 32768
static constexpr int PQ          = PLANES / 4;                  // 8192
static constexpr int LIVE_F4     = PQ * 21 * 8;                 // 1,376,256
static constexpr int ZERO_F8     = PLANES * 11 * 4;             // 1,441,792
static constexpr int LIVE_BLOCKS = LIVE_F4 / THREADS;           // 5376
static constexpr int REM_F8      = ZERO_F8 - LIVE_F4;           // 65,536
static constexpr int REM_BLOCKS  = REM_F8 / THREADS;            // 256

__device__ __forceinline__ void stg256_zero(float* p) {
    asm volatile(
        "st.global.v8.f32 [%0], {%1,%1,%1,%1,%1,%1,%1,%1};"
        :: "l"(p), "f"(0.0f) : "memory");
}

// zero f8 index z -> output float offset
__device__ __forceinline__ float* zero_dst(float* out, int z) {
    int c = z & 3;            // float8 within row (4 per row)
    int r = z >> 2;           // zero-row serial
    int k = r % 11;           // zero-row index within plane
    int p = r / 11;
    int h = 3 * k;            // 0,3,...,30
    return out + (size_t)p * 1024 + h * 32 + c * 8;
}

__global__ void __launch_bounds__(THREADS)
unfoldfold_fused_kernel(const float4* __restrict__ x,
                        float4* __restrict__ out) {
    int b = blockIdx.x;

    if (b < LIVE_BLOCKS) {
        int t = b * THREADS + threadIdx.x;       // [0, LIVE_F4)

        // ---- live-row addressing ----
        int c  = t & 7;                          // float4 column within row
        int r  = t >> 3;                         // live-row serial
        int k  = r % 21;                         // live-row index within plane
        int p0 = r / 21;                         // plane within first chunk
        int h  = (3 * k) / 2 + 1;                // 1,2,4,5,7,8,...,31

        int base = h * 8 + c;
        int i0 = (p0         ) * 256 + base;
        int i1 = (p0 +     PQ) * 256 + base;
        int i2 = (p0 + 2 * PQ) * 256 + base;
        int i3 = (p0 + 3 * PQ) * 256 + base;

        // Issue all 4 loads first (MLP = 4)
        float4 v0 = x[i0];
        float4 v1 = x[i1];
        float4 v2 = x[i2];
        float4 v3 = x[i3];

        // Independent zero store drains write BW inside the load-latency shadow
        stg256_zero(zero_dst((float*)out, t));

        int w0 = c << 2;
        float m0 = (float)(((w0 + 0) % 3) != 0);
        float m1 = (float)(((w0 + 1) % 3) != 0);
        float m2 = (float)(((w0 + 2) % 3) != 0);
        float m3 = (float)(((w0 + 3) % 3) != 0);

        v0.x *= m0; v0.y *= m1; v0.z *= m2; v0.w *= m3;
        v1.x *= m0; v1.y *= m1; v1.z *= m2; v1.w *= m3;
        v2.x *= m0; v2.y *= m1; v2.z *= m2; v2.w *= m3;
        v3.x *= m0; v3.y *= m1; v3.z *= m2; v3.w *= m3;

        out[i0] = v0;
        out[i1] = v1;
        out[i2] = v2;
        out[i3] = v3;
    } else {
        // ---- remainder zero f8s: [LIVE_F4, ZERO_F8) ----
        int z = LIVE_F4 + (b - LIVE_BLOCKS) * THREADS + threadIdx.x;
        stg256_zero(zero_dst((float*)out, z));
    }
}

extern "C" void kernel_launch(void* const* d_in, const int* in_sizes, int n_in,
                              void* d_out, int out_size) {
    const float4* x = (const float4*)d_in[0];
    float4* out     = (float4*)d_out;

    unfoldfold_fused_kernel<<<LIVE_BLOCKS + REM_BLOCKS, THREADS>>>(x, out);
}

// round 12
// speedup vs baseline: 1.0033x; 1.0033x over previous
#include <cuda_runtime.h>

// out[b,c,h,w] = x[b,c,h,w] * (h%3 != 0) * (w%3 != 0)
//
// Unfold(k=2,stride=3,dil=2,pad=1)+fold(identical geometry) == elementwise 0/1
// coverage mask, separable in h,w. Rows h%3==0 are all-zero in the output.
//
// R12 = R10 split-stream winner (live blocks first, separate pure-store zero
// blocks with 256-bit stores) with ONE change: live path uses 8 plane-strided
// unconditional loads per thread (MLP=8) instead of 4.
//
// Geometry: 32768 planes of 32x32 f32; plane = 256 float4; row = 8 float4 =
// one 128B line. Live rows/plane: 21 (h=3k/2+1). Zero rows/plane: 11 (h=3k).

static constexpr int THREADS     = 256;
static constexpr int PLANES      = 64 * 512;                    // 32768
static constexpr int PQ          = PLANES / 8;                  // 4096 (plane chunk)
static constexpr int LIVE_F4     = PQ * 21 * 8;                 // 688,128 per chunk
static constexpr int ZERO_F8     = PLANES * 11 * 4;             // 1,441,792
static constexpr int LIVE_BLOCKS = LIVE_F4 / THREADS;           // 2688
static constexpr int ZERO_BLOCKS = ZERO_F8 / THREADS;           // 5632

__device__ __forceinline__ void stg256_zero(float* p) {
    asm volatile(
        "st.global.v8.f32 [%0], {%1,%1,%1,%1,%1,%1,%1,%1};"
        :: "l"(p), "f"(0.0f) : "memory");
}

__global__ void __launch_bounds__(THREADS)
unfoldfold_split_kernel(const float4* __restrict__ x,
                        float4* __restrict__ out) {
    int b = blockIdx.x;

    if (b < LIVE_BLOCKS) {
        // ---- live rows: 8 batched reads, mask by w, write ----
        int t = b * THREADS + threadIdx.x;       // [0, LIVE_F4)
        int c  = t & 7;                          // float4 column within row
        int r  = t >> 3;                         // live-row serial
        int k  = r % 21;                         // live-row index within plane
        int p0 = r / 21;                         // plane within first chunk
        int h  = (3 * k) / 2 + 1;                // 1,2,4,5,7,8,...,31

        int base = h * 8 + c;

        int idx[8];
#pragma unroll
        for (int j = 0; j < 8; j++)
            idx[j] = (p0 + j * PQ) * 256 + base;

        // 8 unconditional, batched loads (MLP = 8)
        float4 v[8];
#pragma unroll
        for (int j = 0; j < 8; j++)
            v[j] = x[idx[j]];

        int w0 = c << 2;
        float m0 = (float)(((w0 + 0) % 3) != 0);
        float m1 = (float)(((w0 + 1) % 3) != 0);
        float m2 = (float)(((w0 + 2) % 3) != 0);
        float m3 = (float)(((w0 + 3) % 3) != 0);

#pragma unroll
        for (int j = 0; j < 8; j++) {
            v[j].x *= m0; v[j].y *= m1; v[j].z *= m2; v[j].w *= m3;
        }

#pragma unroll
        for (int j = 0; j < 8; j++)
            out[idx[j]] = v[j];
    } else {
        // ---- zero rows: pure 256-bit stores, no loads, no waits ----
        int t = (b - LIVE_BLOCKS) * THREADS + threadIdx.x;   // [0, ZERO_F8)
        int c = t & 3;                           // float8 within row (4 per row)
        int r = t >> 2;                          // zero-row serial
        int k = r % 11;                          // zero-row index within plane
        int p = r / 11;
        int h = 3 * k;                           // 0,3,...,30

        float* dst = (float*)out + (size_t)p * 1024 + h * 32 + c * 8;
        stg256_zero(dst);
    }
}

extern "C" void kernel_launch(void* const* d_in, const int* in_sizes, int n_in,
                              void* d_out, int out_size) {
    const float4* x = (const float4*)d_in[0];
    float4* out     = (float4*)d_out;

    unfoldfold_split_kernel<<<LIVE_BLOCKS + ZERO_BLOCKS, THREADS>>>(x, out);
}